// round 13
// baseline (speedup 1.0000x reference)
#include <cuda_runtime.h>
#include <cuda_fp16.h>
#include <cuda.h>
#include <cstdint>

// ----------------------------------------------------------------------------
// Problem constants
// ----------------------------------------------------------------------------
#define IN_DIM   4096
#define OUT_DIM  4096
#define M_TOTAL  8192          // B*S = 4*2048

#define BM 128
#define BN 256
#define BK 64
#define STAGES 4
#define THREADS 256            // 8 warps: 2 (M) x 4 (N), warp tile 64x64
#define K_ITERS  (IN_DIM / BK)          // 64 chunks per tile
#define TILES_N  (OUT_DIM / BN)         // 16
#define TILES    ((M_TOTAL / BM) * TILES_N)  // 1024

// SMEM layout (relative to 1024-aligned base sb):
//   [0..31]   full barriers (4 x 8B)
//   [64..95]  empty barriers (4 x 8B)
//   [1024 + s*49152]          A tile stage s (128 x 64 halfs, SW128) 16KB
//   [1024 + s*49152 + 16384]  B tile stage s (256 x 64 halfs, SW128) 32KB
#define STAGE_BYTES 49152
#define SMEM_ALLOC  (1024 + STAGES * STAGE_BYTES + 1024)

// ----------------------------------------------------------------------------
// Scratch + cross-CTA readiness state (device globals: allocation-free rule)
// ----------------------------------------------------------------------------
__device__ __half g_w16[(size_t)OUT_DIM * IN_DIM];   // 32MB
__device__ __half g_x16[(size_t)M_TOTAL * IN_DIM];   // 64MB
__device__ unsigned int g_ready[K_ITERS];            // CTAs done with slice k

// ----------------------------------------------------------------------------
// PTX helpers (no tcgen05 — the toolchain targets sm_103 base)
// ----------------------------------------------------------------------------
__device__ __forceinline__ uint32_t smem_u32(const void* p) {
    uint32_t a;
    asm("{ .reg .u64 t; cvta.to.shared.u64 t, %1; cvt.u32.u64 %0, t; }"
        : "=r"(a) : "l"(p));
    return a;
}

#define MBARRIER_INIT(addr, cnt) \
    asm volatile("mbarrier.init.shared.b64 [%0], %1;" :: "r"(addr), "r"(cnt) : "memory")

#define MBARRIER_ARRIVE(addr) \
    asm volatile("mbarrier.arrive.shared.b64 _, [%0];" :: "r"(addr) : "memory")

#define MBARRIER_EXPECT_TX(addr, bytes) \
    asm volatile("mbarrier.arrive.expect_tx.shared.b64 _, [%0], %1;" \
                 :: "r"(addr), "r"(bytes) : "memory")

#define MBARRIER_WAIT_PARITY(addr, parity) do {                                   \
    uint32_t _m = (addr); uint32_t _p = (parity); uint32_t _done;                 \
    asm volatile("{\n\t.reg .pred p;\n\t"                                         \
        "mbarrier.try_wait.parity.acquire.cta.shared::cta.b64 p, [%1], %2;\n\t"   \
        "selp.b32 %0, 1, 0, p;\n\t}"                                              \
        : "=r"(_done) : "r"(_m), "r"(_p) : "memory");                             \
    if (!_done) {                                                                 \
        asm volatile("{\n\t.reg .pred P1;\n\t"                                    \
            "WL_%=:\n\t"                                                          \
            "mbarrier.try_wait.parity.acquire.cta.shared::cta.b64 P1, [%0], %1, 0x989680;\n\t" \
            "@P1 bra.uni WD_%=;\n\t"                                              \
            "bra.uni WL_%=;\n\t"                                                  \
            "WD_%=:\n\t}"                                                         \
            :: "r"(_m), "r"(_p) : "memory");                                      \
    }                                                                             \
} while (0)

#define TMA_LOAD_2D(dst, map_ptr, cx, cy, mbar)                                   \
    asm volatile(                                                                 \
        "cp.async.bulk.tensor.2d.shared::cta.global.tile.mbarrier::complete_tx::bytes " \
        "[%0], [%1, {%2, %3}], [%4];"                                             \
        :: "r"((uint32_t)(dst)), "l"(map_ptr), "r"((int)(cx)), "r"((int)(cy)),    \
           "r"((uint32_t)(mbar)) : "memory")

#define LDSM_X4(r0, r1, r2, r3, addr)                                             \
    asm volatile("ldmatrix.sync.aligned.m8n8.x4.shared.b16 {%0,%1,%2,%3}, [%4];"  \
        : "=r"(r0), "=r"(r1), "=r"(r2), "=r"(r3) : "r"(addr))

#define MMA16816(d, a, b0, b1)                                                    \
    asm volatile(                                                                 \
        "mma.sync.aligned.m16n8k16.row.col.f32.f16.f16.f32 "                      \
        "{%0,%1,%2,%3}, {%4,%5,%6,%7}, {%8,%9}, {%0,%1,%2,%3};"                   \
        : "+f"((d)[0]), "+f"((d)[1]), "+f"((d)[2]), "+f"((d)[3])                  \
        : "r"((a)[0]), "r"((a)[1]), "r"((a)[2]), "r"((a)[3]), "r"(b0), "r"(b1))

// ----------------------------------------------------------------------------
// Reset kernel: zero the per-slice readiness counters (runs before the fused
// kernel on every graph replay — device globals persist across replays).
// ----------------------------------------------------------------------------
__global__ void reset_kernel() {
    if (threadIdx.x < K_ITERS) g_ready[threadIdx.x] = 0u;
}

// ----------------------------------------------------------------------------
// In-kernel prep: convert K-slice `k` (64 columns) of x -> g_x16 and the
// weight tiers -> g_w16, for this CTA's share of rows. All 8 warps; warp w
// handles rows r = 8*cta + w (+ 8*grid strides); lanes cover 2 columns each
// (float2 read / half2 write, fully coalesced 256B per warp-row).
// Low-tier selection uses (wh==0 && wm==0): both tiers are mask-zeroed at
// setup, so masks are redundant. weight_medium arrives promoted to fp32.
// ----------------------------------------------------------------------------
__device__ __forceinline__ void prep_slice(
    int k, int wid, int lane, float s,
    const float* __restrict__ xx, const float* __restrict__ wh,
    const float* __restrict__ wm, const int* __restrict__ wl)
{
    const int col   = k * BK + lane * 2;
    const int rstep = (int)gridDim.x * 8;
    const int rbase = (int)blockIdx.x * 8 + wid;

    // x slice: [M_TOTAL rows] x 64 cols
    for (int r = rbase; r < M_TOTAL; r += rstep) {
        const size_t off = (size_t)r * IN_DIM + col;
        const float2 v = *reinterpret_cast<const float2*>(xx + off);
        *reinterpret_cast<__half2*>(&g_x16[off]) = __floats2half2_rn(v.x, v.y);
    }
    // w slice: [OUT_DIM rows] x 64 cols
    for (int r = rbase; r < OUT_DIM; r += rstep) {
        const size_t off = (size_t)r * IN_DIM + col;
        const float2 h = *reinterpret_cast<const float2*>(wh + off);
        const float2 m = *reinterpret_cast<const float2*>(wm + off);
        const int2   l = *reinterpret_cast<const int2*>(wl + off);
        float f0 = h.x + m.x + ((h.x == 0.0f && m.x == 0.0f) ? (float)l.x * s : 0.0f);
        float f1 = h.y + m.y + ((h.y == 0.0f && m.y == 0.0f) ? (float)l.y * s : 0.0f);
        *reinterpret_cast<__half2*>(&g_w16[off]) = __floats2half2_rn(f0, f1);
    }
}

// ----------------------------------------------------------------------------
// Fused persistent kernel: K-slice prep pipelined into the HMMA GEMM.
//   D = X16[8192,4096] * W16[4096,4096]^T + bias  (fp32 out)
// GEMM core = the measured-best R10/R12 loop (506us, tensor 89.8%, regs 211):
// grouped chunk loop (compile-time stage offsets), precomputed swizzled
// k-offsets, ks-level fragment double buffering, ks3 early stage-release,
// persistent CTAs with continuous chunk stream, rotating producer (g & 7).
// NEW: during the FIRST tile, each chunk-group top preps 4 K-slices (its own
// consumption rate) and releases them via g_ready[k] (threadfence +
// fence.proxy.async before the release atomicAdd); the TMA producer polls
// g_ready before issuing a chunk whose slice may be pending. Prep is pure
// DRAM and the GEMM uses 5% DRAM — they overlap, hiding the former 60us
// serial prep phase inside tile 0's MMA time.
// Deadlock-free: grid = #SMs (all CTAs co-resident) and prep progress never
// depends on GEMM barrier waits.
// ----------------------------------------------------------------------------
struct TileCoord { int m0, n0; };

__device__ __forceinline__ TileCoord tile_coord(int cta, int stride, int ti) {
    int t = cta + ti * stride;
    TileCoord tc;
    tc.n0 = (t & (TILES_N - 1)) * BN;
    tc.m0 = (t >> 4) * BM;
    return tc;
}

__device__ __forceinline__ void issue_chunk(
    int j, int cta, int stride, uint32_t sb,
    const CUtensorMap* pa, const CUtensorMap* pb, uint32_t full0)
{
    TileCoord tc = tile_coord(cta, stride, j >> 6);
    int k = (j & 63) * BK;
    int s = j & (STAGES - 1);
    uint32_t st = sb + 1024 + s * STAGE_BYTES;
    MBARRIER_EXPECT_TX(full0 + s * 8, (uint32_t)STAGE_BYTES);
    TMA_LOAD_2D(st,         pa, k, tc.m0, full0 + s * 8);
    TMA_LOAD_2D(st + 16384, pb, k, tc.n0, full0 + s * 8);
}

__device__ __forceinline__ void poll_slice(int k) {
    while (atomicAdd(&g_ready[k], 0u) < gridDim.x) {}
    asm volatile("fence.proxy.async;" ::: "memory");
}

__global__ void __launch_bounds__(THREADS, 1) fused_kernel(
    const __grid_constant__ CUtensorMap tma_a,
    const __grid_constant__ CUtensorMap tma_b,
    const float* __restrict__ bias,
    float* __restrict__ out,
    const float* __restrict__ xx,
    const float* __restrict__ wh,
    const float* __restrict__ wm,
    const int*   __restrict__ wl,
    const float* __restrict__ scale_p)
{
    extern __shared__ char smem_raw[];
    char* smem = (char*)(((uintptr_t)smem_raw + 1023) & ~(uintptr_t)1023);
    const uint32_t sb = smem_u32(smem);

    const int tid  = threadIdx.x;
    const int wid  = tid >> 5;
    const int lane = tid & 31;
    const int wmw  = wid >> 2;   // 0..1 (M), warp tile M=64
    const int wnw  = wid & 3;    // 0..3 (N), warp tile N=64

    const int cta    = blockIdx.x;
    const int stride = gridDim.x;
    const int cnt    = (TILES - cta + stride - 1) / stride;  // tiles owned
    const int total  = cnt * K_ITERS;                        // chunks owned (mult of 64)

    const uint32_t FULL0  = sb;        // 4 x 8B
    const uint32_t EMPTY0 = sb + 64;   // 4 x 8B

    const float scl = __ldg(scale_p);

    if (tid == 0) {
        #pragma unroll
        for (int s = 0; s < STAGES; ++s) {
            MBARRIER_INIT(FULL0 + s * 8, 1);
            MBARRIER_INIT(EMPTY0 + s * 8, 8);   // 8 warps arrive
        }
        asm volatile("fence.proxy.async.shared::cta;" ::: "memory");
    }
    __syncthreads();

    // ---- Prep prologue: slices 0..2, then release them ----
    prep_slice(0, wid, lane, scl, xx, wh, wm, wl);
    prep_slice(1, wid, lane, scl, xx, wh, wm, wl);
    prep_slice(2, wid, lane, scl, xx, wh, wm, wl);
    __syncthreads();
    if (tid == 0) {
        __threadfence();
        asm volatile("fence.proxy.async;" ::: "memory");
        atomicAdd(&g_ready[0], 1u);
        atomicAdd(&g_ready[1], 1u);
        atomicAdd(&g_ready[2], 1u);
    }

    // TMA prologue: issue chunks 0..STAGES-2 (poll: slices must be chip-ready)
    if (tid == 0) {
        #pragma unroll
        for (int j = 0; j < STAGES - 1; ++j) {
            poll_slice(j);
            issue_chunk(j, cta, stride, sb, &tma_a, &tma_b, FULL0);
        }
    }

    // Per-thread ldmatrix address components (SW128 swizzle on 128B rows)
    const uint32_t a_row = (uint32_t)(wmw * 64 + (lane & 15));
    const uint32_t a_k0  = (uint32_t)((lane >> 4) << 4);            // bytes
    const uint32_t b_row = (uint32_t)(wnw * 64 + (lane & 7) + ((lane >> 4) << 3));
    const uint32_t b_k0  = (uint32_t)(((lane >> 3) & 1) << 4);      // bytes
    const uint32_t swz   = (uint32_t)((lane & 7) << 4);             // same for A & B

    // Hoisted base addresses + precomputed swizzled k-offsets.
    // Full ((ks*32 + k0) ^ swz) precomputed — the XOR spans bits 4-6 which
    // overlap ks*32 (bits 5-6), so it must NOT be split (R9 lesson).
    const uint32_t aBase = sb + 1024 + a_row * 128;
    const uint32_t bBase = sb + 1024 + 16384 + b_row * 128;
    uint32_t aK[4], bK[4];
    #pragma unroll
    for (int ks = 0; ks < 4; ++ks) {
        aK[ks] = ((uint32_t)(ks * 32) + a_k0) ^ swz;
        bK[ks] = ((uint32_t)(ks * 32) + b_k0) ^ swz;
    }

    float c[4][8][4];
    #pragma unroll
    for (int t = 0; t < 4; ++t)
        #pragma unroll
        for (int n = 0; n < 8; ++n)
            #pragma unroll
            for (int k = 0; k < 4; ++k) c[t][n][k] = 0.0f;

    // Double-buffered fragments (ks-level pipelining)
    uint32_t af[2][4][4], bf[2][4][4];

    #pragma unroll 1
    for (int gb = 0; gb < total; gb += STAGES) {
        const int par = (gb >> 2) & 1;   // full-barrier parity, same for group

        // ---- First tile only: prep the next 4 K-slices (matches this
        // group's consumption rate), then release them chip-wide.
        if (gb < K_ITERS) {
            #pragma unroll
            for (int i = 0; i < STAGES; ++i) {
                const int sl = gb + 3 + i;
                if (sl < K_ITERS) prep_slice(sl, wid, lane, scl, xx, wh, wm, wl);
            }
            __syncthreads();
            if (tid == 0) {
                __threadfence();
                asm volatile("fence.proxy.async;" ::: "memory");
                #pragma unroll
                for (int i = 0; i < STAGES; ++i) {
                    const int sl = gb + 3 + i;
                    if (sl < K_ITERS) atomicAdd(&g_ready[sl], 1u);
                }
            }
        }

        #pragma unroll
        for (int s = 0; s < STAGES; ++s) {
            const int g = gb + s;

            // Rotating producer: warp (g & 7), lane 0, issues chunk g+STAGES-1.
            if (wid == (g & 7) && lane == 0) {
                int j = g + STAGES - 1;
                if (j < total) {
                    const int sj = (s + STAGES - 1) & (STAGES - 1);
                    if (j >= STAGES)
                        MBARRIER_WAIT_PARITY(EMPTY0 + sj * 8, ((j >> 2) + 1) & 1);
                    if (j < 2 * K_ITERS) poll_slice(j & 63);  // tiles 0-1: gate on prep
                    issue_chunk(j, cta, stride, sb, &tma_a, &tma_b, FULL0);
                }
            }

            MBARRIER_WAIT_PARITY(FULL0 + s * 8, par);

            const uint32_t aS = aBase + s * STAGE_BYTES;   // compile-time stage term
            const uint32_t bS = bBase + s * STAGE_BYTES;

            // Prefetch ks=0 fragments into buffer 0
            #pragma unroll
            for (int t = 0; t < 4; ++t)
                LDSM_X4(af[0][t][0], af[0][t][1], af[0][t][2], af[0][t][3],
                        aS + t * (16 * 128) + aK[0]);
            #pragma unroll
            for (int gg = 0; gg < 4; ++gg)
                LDSM_X4(bf[0][gg][0], bf[0][gg][1], bf[0][gg][2], bf[0][gg][3],
                        bS + gg * (16 * 128) + bK[0]);

            #pragma unroll
            for (int ks = 0; ks < 4; ++ks) {
                const int cur = ks & 1;
                if (ks < 3) {
                    // Prefetch (g, ks+1) fragments into the other buffer
                    const int nxt = cur ^ 1;
                    #pragma unroll
                    for (int t = 0; t < 4; ++t)
                        LDSM_X4(af[nxt][t][0], af[nxt][t][1], af[nxt][t][2], af[nxt][t][3],
                                aS + t * (16 * 128) + aK[ks + 1]);
                    #pragma unroll
                    for (int gg = 0; gg < 4; ++gg)
                        LDSM_X4(bf[nxt][gg][0], bf[nxt][gg][1], bf[nxt][gg][2], bf[nxt][gg][3],
                                bS + gg * (16 * 128) + bK[ks + 1]);
                } else {
                    // All smem reads for this stage issued; release it so TMA
                    // refills while the final MMA block runs on registers.
                    __syncwarp();
                    if (lane == 0) MBARRIER_ARRIVE(EMPTY0 + s * 8);
                }
                #pragma unroll
                for (int t = 0; t < 4; ++t) {
                    #pragma unroll
                    for (int gg = 0; gg < 4; ++gg) {
                        MMA16816(c[t][2 * gg],     af[cur][t], bf[cur][gg][0], bf[cur][gg][1]);
                        MMA16816(c[t][2 * gg + 1], af[cur][t], bf[cur][gg][2], bf[cur][gg][3]);
                    }
                }
            }

            // ---- Tile boundary: epilogue + accumulator reset (s == 3 only;
            // 64 chunks/tile, 4 | 64). TMA lookahead is already filling the
            // next tile's stages.
            if (s == STAGES - 1 && ((g & 63) == 63)) {
                TileCoord tc = tile_coord(cta, stride, g >> 6);
                const int m_base = tc.m0 + wmw * 64 + (lane >> 2);
                const int n_base = tc.n0 + wnw * 64 + (lane & 3) * 2;

                #pragma unroll
                for (int t = 0; t < 4; ++t) {
                    #pragma unroll
                    for (int nt = 0; nt < 8; ++nt) {
                        const int col = n_base + nt * 8;
                        const float2 bv = *reinterpret_cast<const float2*>(bias + col);
                        const int r0 = m_base + t * 16;
                        float2 v0, v1;
                        v0.x = c[t][nt][0] + bv.x;
                        v0.y = c[t][nt][1] + bv.y;
                        v1.x = c[t][nt][2] + bv.x;
                        v1.y = c[t][nt][3] + bv.y;
                        *reinterpret_cast<float2*>(out + (size_t)r0 * OUT_DIM + col) = v0;
                        *reinterpret_cast<float2*>(out + (size_t)(r0 + 8) * OUT_DIM + col) = v1;
                        c[t][nt][0] = 0.0f; c[t][nt][1] = 0.0f;
                        c[t][nt][2] = 0.0f; c[t][nt][3] = 0.0f;
                    }
                }
            }
        }
    }
}

// ----------------------------------------------------------------------------
// Host launcher
// ----------------------------------------------------------------------------
typedef CUresult (CUDAAPI *PFN_tmap_encode)(
    CUtensorMap*, CUtensorMapDataType, cuuint32_t, void*,
    const cuuint64_t*, const cuuint64_t*, const cuuint32_t*, const cuuint32_t*,
    CUtensorMapInterleave, CUtensorMapSwizzle, CUtensorMapL2promotion,
    CUtensorMapFloatOOBfill);

extern "C" void kernel_launch(void* const* d_in, const int* in_sizes, int n_in,
                              void* d_out, int out_size)
{
    const float*   x    = (const float*)d_in[0];
    const float*   wh   = (const float*)d_in[1];
    const float*   wmed = (const float*)d_in[2];   // fp16 promoted to fp32 by harness
    const int*     wl   = (const int*)d_in[3];
    const float*   ls   = (const float*)d_in[6];
    const float*   bias = (const float*)d_in[7];
    float* out = (float*)d_out;

    void* w16p = nullptr;
    void* x16p = nullptr;
    cudaGetSymbolAddress(&w16p, g_w16);
    cudaGetSymbolAddress(&x16p, g_x16);

    // Resolve cuTensorMapEncodeTiled through the runtime (no -lcuda needed).
    PFN_tmap_encode encode = nullptr;
    cudaDriverEntryPointQueryResult qres;
    cudaGetDriverEntryPointByVersion("cuTensorMapEncodeTiled", (void**)&encode,
                                     12000, cudaEnableDefault, &qres);

    CUtensorMap tma_a, tma_b;
    {
        cuuint64_t dims[2]    = { IN_DIM, M_TOTAL };
        cuuint64_t strides[1] = { IN_DIM * sizeof(__half) };
        cuuint32_t box[2]     = { BK, BM };           // 64 x 128
        cuuint32_t es[2]      = { 1, 1 };
        encode(&tma_a, CU_TENSOR_MAP_DATA_TYPE_FLOAT16, 2, x16p,
               dims, strides, box, es,
               CU_TENSOR_MAP_INTERLEAVE_NONE, CU_TENSOR_MAP_SWIZZLE_128B,
               CU_TENSOR_MAP_L2_PROMOTION_L2_128B, CU_TENSOR_MAP_FLOAT_OOB_FILL_NONE);
    }
    {
        cuuint64_t dims[2]    = { IN_DIM, OUT_DIM };
        cuuint64_t strides[1] = { IN_DIM * sizeof(__half) };
        cuuint32_t box[2]     = { BK, BN };           // 64 x 256
        cuuint32_t es[2]      = { 1, 1 };
        encode(&tma_b, CU_TENSOR_MAP_DATA_TYPE_FLOAT16, 2, w16p,
               dims, strides, box, es,
               CU_TENSOR_MAP_INTERLEAVE_NONE, CU_TENSOR_MAP_SWIZZLE_128B,
               CU_TENSOR_MAP_L2_PROMOTION_L2_128B, CU_TENSOR_MAP_FLOAT_OOB_FILL_NONE);
    }

    // Reset per-slice readiness counters (graph replays reuse device globals).
    reset_kernel<<<1, K_ITERS>>>();

    // Fused persistent prep+GEMM — one CTA per SM.
    int dev = 0, sm_count = 148;
    cudaGetDevice(&dev);
    cudaDeviceGetAttribute(&sm_count, cudaDevAttrMultiProcessorCount, dev);
    if (sm_count > TILES) sm_count = TILES;
    cudaFuncSetAttribute(fused_kernel,
                         cudaFuncAttributeMaxDynamicSharedMemorySize, SMEM_ALLOC);
    fused_kernel<<<sm_count, THREADS, SMEM_ALLOC>>>(
        tma_a, tma_b, bias, out, x, wh, wmed, wl, ls);
}

// round 14
// speedup vs baseline: 1.7525x; 1.7525x over previous
#include <cuda_runtime.h>
#include <cuda_fp16.h>
#include <cuda.h>
#include <cstdint>

// ----------------------------------------------------------------------------
// Problem constants
// ----------------------------------------------------------------------------
#define IN_DIM   4096
#define OUT_DIM  4096
#define M_TOTAL  8192          // B*S = 4*2048

#define BM 128
#define BN 256
#define BK 64
#define STAGES 4
#define THREADS 256            // 8 warps: 2 (M) x 4 (N), warp tile 64x64
#define K_ITERS  (IN_DIM / BK)          // 64 chunks per tile
#define TILES_N  (OUT_DIM / BN)         // 16
#define TILES    ((M_TOTAL / BM) * TILES_N)  // 1024

// SMEM layout (relative to 1024-aligned base sb):
//   [0..31]   full barriers (4 x 8B)
//   [64..95]  empty barriers (4 x 8B)
//   [1024 + s*49152]          A tile stage s (128 x 64 halfs, SW128) 16KB
//   [1024 + s*49152 + 16384]  B tile stage s (256 x 64 halfs, SW128) 32KB
#define STAGE_BYTES 49152
#define SMEM_ALLOC  (1024 + STAGES * STAGE_BYTES + 1024)

// ----------------------------------------------------------------------------
// Scratch (device globals: allocation-free rule)
// ----------------------------------------------------------------------------
__device__ __half g_w16[(size_t)OUT_DIM * IN_DIM];   // 32MB
__device__ __half g_x16[(size_t)M_TOTAL * IN_DIM];   // 64MB

// ----------------------------------------------------------------------------
// PTX helpers (no tcgen05 — the toolchain targets sm_103 base)
// ----------------------------------------------------------------------------
__device__ __forceinline__ uint32_t smem_u32(const void* p) {
    uint32_t a;
    asm("{ .reg .u64 t; cvta.to.shared.u64 t, %1; cvt.u32.u64 %0, t; }"
        : "=r"(a) : "l"(p));
    return a;
}

#define MBARRIER_INIT(addr, cnt) \
    asm volatile("mbarrier.init.shared.b64 [%0], %1;" :: "r"(addr), "r"(cnt) : "memory")

#define MBARRIER_ARRIVE(addr) \
    asm volatile("mbarrier.arrive.shared.b64 _, [%0];" :: "r"(addr) : "memory")

#define MBARRIER_EXPECT_TX(addr, bytes) \
    asm volatile("mbarrier.arrive.expect_tx.shared.b64 _, [%0], %1;" \
                 :: "r"(addr), "r"(bytes) : "memory")

#define MBARRIER_WAIT_PARITY(addr, parity) do {                                   \
    uint32_t _m = (addr); uint32_t _p = (parity); uint32_t _done;                 \
    asm volatile("{\n\t.reg .pred p;\n\t"                                         \
        "mbarrier.try_wait.parity.acquire.cta.shared::cta.b64 p, [%1], %2;\n\t"   \
        "selp.b32 %0, 1, 0, p;\n\t}"                                              \
        : "=r"(_done) : "r"(_m), "r"(_p) : "memory");                             \
    if (!_done) {                                                                 \
        asm volatile("{\n\t.reg .pred P1;\n\t"                                    \
            "WL_%=:\n\t"                                                          \
            "mbarrier.try_wait.parity.acquire.cta.shared::cta.b64 P1, [%0], %1, 0x989680;\n\t" \
            "@P1 bra.uni WD_%=;\n\t"                                              \
            "bra.uni WL_%=;\n\t"                                                  \
            "WD_%=:\n\t}"                                                         \
            :: "r"(_m), "r"(_p) : "memory");                                      \
    }                                                                             \
} while (0)

#define TMA_LOAD_2D(dst, map_ptr, cx, cy, mbar)                                   \
    asm volatile(                                                                 \
        "cp.async.bulk.tensor.2d.shared::cta.global.tile.mbarrier::complete_tx::bytes " \
        "[%0], [%1, {%2, %3}], [%4];"                                             \
        :: "r"((uint32_t)(dst)), "l"(map_ptr), "r"((int)(cx)), "r"((int)(cy)),    \
           "r"((uint32_t)(mbar)) : "memory")

#define LDSM_X4(r0, r1, r2, r3, addr)                                             \
    asm volatile("ldmatrix.sync.aligned.m8n8.x4.shared.b16 {%0,%1,%2,%3}, [%4];"  \
        : "=r"(r0), "=r"(r1), "=r"(r2), "=r"(r3) : "r"(addr))

#define MMA16816(d, a, b0, b1)                                                    \
    asm volatile(                                                                 \
        "mma.sync.aligned.m16n8k16.row.col.f32.f16.f16.f32 "                      \
        "{%0,%1,%2,%3}, {%4,%5,%6,%7}, {%8,%9}, {%0,%1,%2,%3};"                   \
        : "+f"((d)[0]), "+f"((d)[1]), "+f"((d)[2]), "+f"((d)[3])                  \
        : "r"((a)[0]), "r"((a)[1]), "r"((a)[2]), "r"((a)[3]), "r"(b0), "r"(b1))

// ----------------------------------------------------------------------------
// Kernel 1: fused prep. blockIdx.y == 0 -> weight reconstruction,
//           blockIdx.y == 1 -> x fp32 -> fp16 conversion.
// Low-tier selection uses (wh==0 && wm==0): weight_high / weight_medium are
// mask-zeroed at setup, so masks are redundant (avoids bool-dtype ambiguity).
// weight_medium arrives promoted to float32 by the harness.
// Measured at the DRAM roofline (416MB total traffic, ~6.9TB/s).
// ----------------------------------------------------------------------------
__global__ void __launch_bounds__(256) prep_kernel(
    const float4* __restrict__ wh, const float4* __restrict__ wmed,
    const int4* __restrict__ wl, const float* __restrict__ scale_p,
    uint2* __restrict__ w16,
    const float4* __restrict__ x, uint4* __restrict__ x16)
{
    int i = blockIdx.x * blockDim.x + threadIdx.x;
    if (blockIdx.y == 0) {
        float s = __ldg(scale_p);
        float4 h = wh[i];
        float4 m = wmed[i];
        int4  l = wl[i];

        float f0 = h.x + m.x + ((h.x == 0.0f && m.x == 0.0f) ? (float)l.x * s : 0.0f);
        float f1 = h.y + m.y + ((h.y == 0.0f && m.y == 0.0f) ? (float)l.y * s : 0.0f);
        float f2 = h.z + m.z + ((h.z == 0.0f && m.z == 0.0f) ? (float)l.z * s : 0.0f);
        float f3 = h.w + m.w + ((h.w == 0.0f && m.w == 0.0f) ? (float)l.w * s : 0.0f);

        __half2 o01 = __floats2half2_rn(f0, f1);
        __half2 o23 = __floats2half2_rn(f2, f3);
        uint2 o;
        o.x = *reinterpret_cast<uint32_t*>(&o01);
        o.y = *reinterpret_cast<uint32_t*>(&o23);
        w16[i] = o;
    } else {
        float4 a = x[2 * i], b = x[2 * i + 1];
        __half2 p0 = __floats2half2_rn(a.x, a.y);
        __half2 p1 = __floats2half2_rn(a.z, a.w);
        __half2 p2 = __floats2half2_rn(b.x, b.y);
        __half2 p3 = __floats2half2_rn(b.z, b.w);
        uint4 o;
        o.x = *reinterpret_cast<uint32_t*>(&p0);
        o.y = *reinterpret_cast<uint32_t*>(&p1);
        o.z = *reinterpret_cast<uint32_t*>(&p2);
        o.w = *reinterpret_cast<uint32_t*>(&p3);
        x16[i] = o;
    }
}

// ----------------------------------------------------------------------------
// Kernel 2: persistent HMMA fp16 GEMM (fp32 accum), 128x256 tiles.
//   D = X16[8192,4096] * W16[4096,4096]^T + bias  (fp32 out)
// 8 warps: 2 (M) x 4 (N); warp tile 64 x 64; mma.m16n8k16.
// The measured-best configuration (R10/R12: ~506us GEMM, tensor 89.8%,
// regs 211, fma 0.3%):
//  - grouped chunk loop: stage offsets are compile-time immediates (no
//    integer rematerialization — R8/R11 showed live-range pressure costs
//    8-13% in fma/alu issue slots)
//  - precomputed swizzled k-offsets aK/bK = ((ks*32+k0)^swz) — the XOR spans
//    bits 4-6 overlapping ks*32, so it must not be split (R9 NaN)
//  - wait-full at chunk top; ks-level fragment double buffering; ks3 early
//    stage-release so TMA refills during the trailing MMA block
//  - persistent CTAs with continuous chunk stream (parity never resets;
//    lookahead prefetches the next tile during the epilogue)
//  - rotating producer (g & 7) so no warp is the permanent straggler.
// Tried and rejected with evidence: early boundary-cross (3x: register
// live-range -> address rematerialization), in-kernel prep overlap (1x:
// chip-wide convoy serialization, tensor 45%). Do not revisit.
// ----------------------------------------------------------------------------
struct TileCoord { int m0, n0; };

__device__ __forceinline__ TileCoord tile_coord(int cta, int stride, int ti) {
    int t = cta + ti * stride;
    TileCoord tc;
    tc.n0 = (t & (TILES_N - 1)) * BN;
    tc.m0 = (t >> 4) * BM;
    return tc;
}

__device__ __forceinline__ void issue_chunk(
    int j, int cta, int stride, uint32_t sb,
    const CUtensorMap* pa, const CUtensorMap* pb, uint32_t full0)
{
    TileCoord tc = tile_coord(cta, stride, j >> 6);
    int k = (j & 63) * BK;
    int s = j & (STAGES - 1);
    uint32_t st = sb + 1024 + s * STAGE_BYTES;
    MBARRIER_EXPECT_TX(full0 + s * 8, (uint32_t)STAGE_BYTES);
    TMA_LOAD_2D(st,         pa, k, tc.m0, full0 + s * 8);
    TMA_LOAD_2D(st + 16384, pb, k, tc.n0, full0 + s * 8);
}

__global__ void __launch_bounds__(THREADS, 1) gemm_f16_kernel(
    const __grid_constant__ CUtensorMap tma_a,
    const __grid_constant__ CUtensorMap tma_b,
    const float* __restrict__ bias,
    float* __restrict__ out)
{
    extern __shared__ char smem_raw[];
    char* smem = (char*)(((uintptr_t)smem_raw + 1023) & ~(uintptr_t)1023);
    const uint32_t sb = smem_u32(smem);

    const int tid  = threadIdx.x;
    const int wid  = tid >> 5;
    const int lane = tid & 31;
    const int wm   = wid >> 2;   // 0..1 (M), warp tile M=64
    const int wn   = wid & 3;    // 0..3 (N), warp tile N=64

    const int cta    = blockIdx.x;
    const int stride = gridDim.x;
    const int cnt    = (TILES - cta + stride - 1) / stride;  // tiles owned
    const int total  = cnt * K_ITERS;                        // chunks owned (mult of 64)

    const uint32_t FULL0  = sb;        // 4 x 8B
    const uint32_t EMPTY0 = sb + 64;   // 4 x 8B

    if (tid == 0) {
        #pragma unroll
        for (int s = 0; s < STAGES; ++s) {
            MBARRIER_INIT(FULL0 + s * 8, 1);
            MBARRIER_INIT(EMPTY0 + s * 8, 8);   // 8 warps arrive
        }
        asm volatile("fence.proxy.async.shared::cta;" ::: "memory");
    }
    __syncthreads();

    // Prologue: issue chunks 0..STAGES-2
    if (tid == 0) {
        #pragma unroll
        for (int j = 0; j < STAGES - 1; ++j)
            if (j < total) issue_chunk(j, cta, stride, sb, &tma_a, &tma_b, FULL0);
    }

    // Per-thread ldmatrix address components (SW128 swizzle on 128B rows)
    const uint32_t a_row = (uint32_t)(wm * 64 + (lane & 15));
    const uint32_t a_k0  = (uint32_t)((lane >> 4) << 4);            // bytes
    const uint32_t b_row = (uint32_t)(wn * 64 + (lane & 7) + ((lane >> 4) << 3));
    const uint32_t b_k0  = (uint32_t)(((lane >> 3) & 1) << 4);      // bytes
    const uint32_t swz   = (uint32_t)((lane & 7) << 4);             // same for A & B

    // Hoisted per-thread base addresses and precomputed swizzled k-offsets.
    // Full expression ((ks*32 + k0) ^ swz) precomputed — XOR covers bits 4-6
    // which overlap ks*32 (bits 5-6), so it must NOT be split.
    const uint32_t aBase = sb + 1024 + a_row * 128;
    const uint32_t bBase = sb + 1024 + 16384 + b_row * 128;
    uint32_t aK[4], bK[4];
    #pragma unroll
    for (int ks = 0; ks < 4; ++ks) {
        aK[ks] = ((uint32_t)(ks * 32) + a_k0) ^ swz;
        bK[ks] = ((uint32_t)(ks * 32) + b_k0) ^ swz;
    }

    float c[4][8][4];
    #pragma unroll
    for (int t = 0; t < 4; ++t)
        #pragma unroll
        for (int n = 0; n < 8; ++n)
            #pragma unroll
            for (int k = 0; k < 4; ++k) c[t][n][k] = 0.0f;

    // Double-buffered fragments (ks-level pipelining)
    uint32_t af[2][4][4], bf[2][4][4];

    #pragma unroll 1
    for (int gb = 0; gb < total; gb += STAGES) {
        const int par = (gb >> 2) & 1;   // full-barrier parity, same for group

        #pragma unroll
        for (int s = 0; s < STAGES; ++s) {
            const int g = gb + s;

            // Rotating producer: warp (g & 7), lane 0, issues chunk g+STAGES-1.
            if (wid == (g & 7) && lane == 0) {
                int j = g + STAGES - 1;
                if (j < total) {
                    const int sj = (s + STAGES - 1) & (STAGES - 1);
                    if (j >= STAGES)
                        MBARRIER_WAIT_PARITY(EMPTY0 + sj * 8, ((j >> 2) + 1) & 1);
                    issue_chunk(j, cta, stride, sb, &tma_a, &tma_b, FULL0);
                }
            }

            MBARRIER_WAIT_PARITY(FULL0 + s * 8, par);

            const uint32_t aS = aBase + s * STAGE_BYTES;   // compile-time stage term
            const uint32_t bS = bBase + s * STAGE_BYTES;

            // Prefetch ks=0 fragments into buffer 0
            #pragma unroll
            for (int t = 0; t < 4; ++t)
                LDSM_X4(af[0][t][0], af[0][t][1], af[0][t][2], af[0][t][3],
                        aS + t * (16 * 128) + aK[0]);
            #pragma unroll
            for (int gg = 0; gg < 4; ++gg)
                LDSM_X4(bf[0][gg][0], bf[0][gg][1], bf[0][gg][2], bf[0][gg][3],
                        bS + gg * (16 * 128) + bK[0]);

            #pragma unroll
            for (int ks = 0; ks < 4; ++ks) {
                const int cur = ks & 1;
                if (ks < 3) {
                    // Prefetch (g, ks+1) fragments into the other buffer
                    const int nxt = cur ^ 1;
                    #pragma unroll
                    for (int t = 0; t < 4; ++t)
                        LDSM_X4(af[nxt][t][0], af[nxt][t][1], af[nxt][t][2], af[nxt][t][3],
                                aS + t * (16 * 128) + aK[ks + 1]);
                    #pragma unroll
                    for (int gg = 0; gg < 4; ++gg)
                        LDSM_X4(bf[nxt][gg][0], bf[nxt][gg][1], bf[nxt][gg][2], bf[nxt][gg][3],
                                bS + gg * (16 * 128) + bK[ks + 1]);
                } else {
                    // All smem reads for this stage issued; release it so TMA
                    // refills while the final MMA block runs on registers.
                    __syncwarp();
                    if (lane == 0) MBARRIER_ARRIVE(EMPTY0 + s * 8);
                }
                #pragma unroll
                for (int t = 0; t < 4; ++t) {
                    #pragma unroll
                    for (int gg = 0; gg < 4; ++gg) {
                        MMA16816(c[t][2 * gg],     af[cur][t], bf[cur][gg][0], bf[cur][gg][1]);
                        MMA16816(c[t][2 * gg + 1], af[cur][t], bf[cur][gg][2], bf[cur][gg][3]);
                    }
                }
            }

            // ---- Tile boundary: epilogue + accumulator reset. Reachable only
            // at s == 3 (64 chunks/tile, 4 | 64). TMA lookahead is already
            // filling the next tile's stages.
            if (s == STAGES - 1 && ((g & 63) == 63)) {
                TileCoord tc = tile_coord(cta, stride, g >> 6);
                const int m_base = tc.m0 + wm * 64 + (lane >> 2);
                const int n_base = tc.n0 + wn * 64 + (lane & 3) * 2;

                #pragma unroll
                for (int t = 0; t < 4; ++t) {
                    #pragma unroll
                    for (int nt = 0; nt < 8; ++nt) {
                        const int col = n_base + nt * 8;
                        const float2 bv = *reinterpret_cast<const float2*>(bias + col);
                        const int r0 = m_base + t * 16;
                        float2 v0, v1;
                        v0.x = c[t][nt][0] + bv.x;
                        v0.y = c[t][nt][1] + bv.y;
                        v1.x = c[t][nt][2] + bv.x;
                        v1.y = c[t][nt][3] + bv.y;
                        *reinterpret_cast<float2*>(out + (size_t)r0 * OUT_DIM + col) = v0;
                        *reinterpret_cast<float2*>(out + (size_t)(r0 + 8) * OUT_DIM + col) = v1;
                        c[t][nt][0] = 0.0f; c[t][nt][1] = 0.0f;
                        c[t][nt][2] = 0.0f; c[t][nt][3] = 0.0f;
                    }
                }
            }
        }
    }
}

// ----------------------------------------------------------------------------
// Host launcher
// ----------------------------------------------------------------------------
typedef CUresult (CUDAAPI *PFN_tmap_encode)(
    CUtensorMap*, CUtensorMapDataType, cuuint32_t, void*,
    const cuuint64_t*, const cuuint64_t*, const cuuint32_t*, const cuuint32_t*,
    CUtensorMapInterleave, CUtensorMapSwizzle, CUtensorMapL2promotion,
    CUtensorMapFloatOOBfill);

extern "C" void kernel_launch(void* const* d_in, const int* in_sizes, int n_in,
                              void* d_out, int out_size)
{
    const float*   x    = (const float*)d_in[0];
    const float*   wh   = (const float*)d_in[1];
    const float*   wmed = (const float*)d_in[2];   // fp16 promoted to fp32 by harness
    const int*     wl   = (const int*)d_in[3];
    const float*   ls   = (const float*)d_in[6];
    const float*   bias = (const float*)d_in[7];
    float* out = (float*)d_out;

    void* w16p = nullptr;
    void* x16p = nullptr;
    cudaGetSymbolAddress(&w16p, g_w16);
    cudaGetSymbolAddress(&x16p, g_x16);

    // Resolve cuTensorMapEncodeTiled through the runtime (no -lcuda needed).
    PFN_tmap_encode encode = nullptr;
    cudaDriverEntryPointQueryResult qres;
    cudaGetDriverEntryPointByVersion("cuTensorMapEncodeTiled", (void**)&encode,
                                     12000, cudaEnableDefault, &qres);

    CUtensorMap tma_a, tma_b;
    {
        cuuint64_t dims[2]    = { IN_DIM, M_TOTAL };
        cuuint64_t strides[1] = { IN_DIM * sizeof(__half) };
        cuuint32_t box[2]     = { BK, BM };           // 64 x 128
        cuuint32_t es[2]      = { 1, 1 };
        encode(&tma_a, CU_TENSOR_MAP_DATA_TYPE_FLOAT16, 2, x16p,
               dims, strides, box, es,
               CU_TENSOR_MAP_INTERLEAVE_NONE, CU_TENSOR_MAP_SWIZZLE_128B,
               CU_TENSOR_MAP_L2_PROMOTION_L2_128B, CU_TENSOR_MAP_FLOAT_OOB_FILL_NONE);
    }
    {
        cuuint64_t dims[2]    = { IN_DIM, OUT_DIM };
        cuuint64_t strides[1] = { IN_DIM * sizeof(__half) };
        cuuint32_t box[2]     = { BK, BN };           // 64 x 256
        cuuint32_t es[2]      = { 1, 1 };
        encode(&tma_b, CU_TENSOR_MAP_DATA_TYPE_FLOAT16, 2, w16p,
               dims, strides, box, es,
               CU_TENSOR_MAP_INTERLEAVE_NONE, CU_TENSOR_MAP_SWIZZLE_128B,
               CU_TENSOR_MAP_L2_PROMOTION_L2_128B, CU_TENSOR_MAP_FLOAT_OOB_FILL_NONE);
    }

    // Kernel 1: fused weight reconstruction + x conversion.
    dim3 pgrid((OUT_DIM * IN_DIM / 4) / 256, 2);
    prep_kernel<<<pgrid, 256>>>(
        (const float4*)wh, (const float4*)wmed, (const int4*)wl, ls,
        (uint2*)w16p, (const float4*)x, (uint4*)x16p);

    // Kernel 2: persistent GEMM — one CTA per SM.
    int dev = 0, sm_count = 148;
    cudaGetDevice(&dev);
    cudaDeviceGetAttribute(&sm_count, cudaDevAttrMultiProcessorCount, dev);
    if (sm_count > TILES) sm_count = TILES;
    cudaFuncSetAttribute(gemm_f16_kernel,
                         cudaFuncAttributeMaxDynamicSharedMemorySize, SMEM_ALLOC);
    gemm_f16_kernel<<<sm_count, THREADS, SMEM_ALLOC>>>(tma_a, tma_b, bias, out);
}

// round 15
// speedup vs baseline: 1.7541x; 1.0009x over previous
#include <cuda_runtime.h>
#include <cuda_fp16.h>
#include <cuda.h>
#include <cstdint>

// ----------------------------------------------------------------------------
// Problem constants
// ----------------------------------------------------------------------------
#define IN_DIM   4096
#define OUT_DIM  4096
#define M_TOTAL  8192          // B*S = 4*2048

#define BM 128
#define BN 256
#define BK 64
#define STAGES 4
#define THREADS 256            // 8 warps: 2 (M) x 4 (N), warp tile 64x64
#define K_ITERS  (IN_DIM / BK)          // 64 chunks per tile
#define TILES_N  (OUT_DIM / BN)         // 16
#define TILES    ((M_TOTAL / BM) * TILES_N)  // 1024

// SMEM layout (relative to 1024-aligned base sb):
//   [0..31]   full barriers (4 x 8B)
//   [64..95]  empty barriers (4 x 8B)
//   [1024 + s*49152]          A tile stage s (128 x 64 halfs, SW128) 16KB
//   [1024 + s*49152 + 16384]  B tile stage s (256 x 64 halfs, SW128) 32KB
#define STAGE_BYTES 49152
#define SMEM_ALLOC  (1024 + STAGES * STAGE_BYTES + 1024)

// Prep: two independent coalesced streams per thread (MLP boost).
#define W_GROUPS   (OUT_DIM * IN_DIM / 4)      // float4-groups in w (4.19M)
#define W_HALF     (W_GROUPS / 2)
#define X_GROUPS   ((M_TOTAL * IN_DIM) / 8)    // 8-elem groups in x (4.19M)
#define X_HALF     (X_GROUPS / 2)
#define PREP_BLKS  (W_HALF / 256)              // 8192

// ----------------------------------------------------------------------------
// Scratch (device globals: allocation-free rule)
// ----------------------------------------------------------------------------
__device__ __half g_w16[(size_t)OUT_DIM * IN_DIM];   // 32MB
__device__ __half g_x16[(size_t)M_TOTAL * IN_DIM];   // 64MB

// ----------------------------------------------------------------------------
// PTX helpers (no tcgen05 — the toolchain targets sm_103 base)
// ----------------------------------------------------------------------------
__device__ __forceinline__ uint32_t smem_u32(const void* p) {
    uint32_t a;
    asm("{ .reg .u64 t; cvta.to.shared.u64 t, %1; cvt.u32.u64 %0, t; }"
        : "=r"(a) : "l"(p));
    return a;
}

#define MBARRIER_INIT(addr, cnt) \
    asm volatile("mbarrier.init.shared.b64 [%0], %1;" :: "r"(addr), "r"(cnt) : "memory")

#define MBARRIER_ARRIVE(addr) \
    asm volatile("mbarrier.arrive.shared.b64 _, [%0];" :: "r"(addr) : "memory")

#define MBARRIER_EXPECT_TX(addr, bytes) \
    asm volatile("mbarrier.arrive.expect_tx.shared.b64 _, [%0], %1;" \
                 :: "r"(addr), "r"(bytes) : "memory")

#define MBARRIER_WAIT_PARITY(addr, parity) do {                                   \
    uint32_t _m = (addr); uint32_t _p = (parity); uint32_t _done;                 \
    asm volatile("{\n\t.reg .pred p;\n\t"                                         \
        "mbarrier.try_wait.parity.acquire.cta.shared::cta.b64 p, [%1], %2;\n\t"   \
        "selp.b32 %0, 1, 0, p;\n\t}"                                              \
        : "=r"(_done) : "r"(_m), "r"(_p) : "memory");                             \
    if (!_done) {                                                                 \
        asm volatile("{\n\t.reg .pred P1;\n\t"                                    \
            "WL_%=:\n\t"                                                          \
            "mbarrier.try_wait.parity.acquire.cta.shared::cta.b64 P1, [%0], %1, 0x989680;\n\t" \
            "@P1 bra.uni WD_%=;\n\t"                                              \
            "bra.uni WL_%=;\n\t"                                                  \
            "WD_%=:\n\t}"                                                         \
            :: "r"(_m), "r"(_p) : "memory");                                      \
    }                                                                             \
} while (0)

#define TMA_LOAD_2D(dst, map_ptr, cx, cy, mbar)                                   \
    asm volatile(                                                                 \
        "cp.async.bulk.tensor.2d.shared::cta.global.tile.mbarrier::complete_tx::bytes " \
        "[%0], [%1, {%2, %3}], [%4];"                                             \
        :: "r"((uint32_t)(dst)), "l"(map_ptr), "r"((int)(cx)), "r"((int)(cy)),    \
           "r"((uint32_t)(mbar)) : "memory")

#define LDSM_X4(r0, r1, r2, r3, addr)                                             \
    asm volatile("ldmatrix.sync.aligned.m8n8.x4.shared.b16 {%0,%1,%2,%3}, [%4];"  \
        : "=r"(r0), "=r"(r1), "=r"(r2), "=r"(r3) : "r"(addr))

#define MMA16816(d, a, b0, b1)                                                    \
    asm volatile(                                                                 \
        "mma.sync.aligned.m16n8k16.row.col.f32.f16.f16.f32 "                      \
        "{%0,%1,%2,%3}, {%4,%5,%6,%7}, {%8,%9}, {%0,%1,%2,%3};"                   \
        : "+f"((d)[0]), "+f"((d)[1]), "+f"((d)[2]), "+f"((d)[3])                  \
        : "r"((a)[0]), "r"((a)[1]), "r"((a)[2]), "r"((a)[3]), "r"(b0), "r"(b1))

// ----------------------------------------------------------------------------
// Kernel 1: fused prep. blockIdx.y == 0 -> weight reconstruction,
//           blockIdx.y == 1 -> x fp32 -> fp16 conversion.
// Each thread processes TWO independent, fully-coalesced streams (index i and
// i + half_range): doubles memory-level parallelism so the DRAM pipe stays
// saturated (standalone profile showed 80% DRAM with single-stream threads —
// exposure was per-thread MLP, not bandwidth).
// Low-tier selection uses (wh==0 && wm==0): weight_high / weight_medium are
// mask-zeroed at setup, so masks are redundant (avoids bool-dtype ambiguity).
// weight_medium arrives promoted to float32 by the harness.
// ----------------------------------------------------------------------------
__device__ __forceinline__ uint2 w_group(const float4& h, const float4& m,
                                         const int4& l, float s) {
    float f0 = h.x + m.x + ((h.x == 0.0f && m.x == 0.0f) ? (float)l.x * s : 0.0f);
    float f1 = h.y + m.y + ((h.y == 0.0f && m.y == 0.0f) ? (float)l.y * s : 0.0f);
    float f2 = h.z + m.z + ((h.z == 0.0f && m.z == 0.0f) ? (float)l.z * s : 0.0f);
    float f3 = h.w + m.w + ((h.w == 0.0f && m.w == 0.0f) ? (float)l.w * s : 0.0f);
    __half2 o01 = __floats2half2_rn(f0, f1);
    __half2 o23 = __floats2half2_rn(f2, f3);
    uint2 o;
    o.x = *reinterpret_cast<uint32_t*>(&o01);
    o.y = *reinterpret_cast<uint32_t*>(&o23);
    return o;
}

__device__ __forceinline__ uint4 x_group(const float4& a, const float4& b) {
    __half2 p0 = __floats2half2_rn(a.x, a.y);
    __half2 p1 = __floats2half2_rn(a.z, a.w);
    __half2 p2 = __floats2half2_rn(b.x, b.y);
    __half2 p3 = __floats2half2_rn(b.z, b.w);
    uint4 o;
    o.x = *reinterpret_cast<uint32_t*>(&p0);
    o.y = *reinterpret_cast<uint32_t*>(&p1);
    o.z = *reinterpret_cast<uint32_t*>(&p2);
    o.w = *reinterpret_cast<uint32_t*>(&p3);
    return o;
}

__global__ void __launch_bounds__(256) prep_kernel(
    const float4* __restrict__ wh, const float4* __restrict__ wmed,
    const int4* __restrict__ wl, const float* __restrict__ scale_p,
    uint2* __restrict__ w16,
    const float4* __restrict__ x, uint4* __restrict__ x16)
{
    int i = blockIdx.x * blockDim.x + threadIdx.x;
    if (blockIdx.y == 0) {
        // ---- weight reconstruction: 2 independent float4-groups/thread ----
        float s = __ldg(scale_p);
        const int j = i + W_HALF;
        // Issue all 6 loads before any compute (MLP = 6)
        float4 h0 = wh[i],   h1 = wh[j];
        float4 m0 = wmed[i], m1 = wmed[j];
        int4   l0 = wl[i],   l1 = wl[j];
        w16[i] = w_group(h0, m0, l0, s);
        w16[j] = w_group(h1, m1, l1, s);
    } else {
        // ---- x conversion: 2 independent 8-elem groups/thread (MLP = 4) ----
        const int j = i + X_HALF;
        float4 a0 = x[2 * i], b0 = x[2 * i + 1];
        float4 a1 = x[2 * j], b1 = x[2 * j + 1];
        x16[i] = x_group(a0, b0);
        x16[j] = x_group(a1, b1);
    }
}

// ----------------------------------------------------------------------------
// Kernel 2: persistent HMMA fp16 GEMM (fp32 accum), 128x256 tiles.
//   D = X16[8192,4096] * W16[4096,4096]^T + bias  (fp32 out)
// 8 warps: 2 (M) x 4 (N); warp tile 64 x 64; mma.m16n8k16.
// The measured-best configuration (R10/R12/R14: ~505us GEMM, tensor 89.8%,
// regs 211, fma 0.3% — at the mma.sync issue floor x ceil(1024/152) tiles):
//  - grouped chunk loop: stage offsets are compile-time immediates (no
//    integer rematerialization — R8/R11 showed live-range pressure costs
//    8-13% in fma/alu issue slots)
//  - precomputed swizzled k-offsets aK/bK = ((ks*32+k0)^swz) — the XOR spans
//    bits 4-6 overlapping ks*32, so it must not be split (R9 NaN)
//  - wait-full at chunk top; ks-level fragment double buffering; ks3 early
//    stage-release so TMA refills during the trailing MMA block
//  - persistent CTAs with continuous chunk stream (parity never resets;
//    lookahead prefetches the next tile during the epilogue)
//  - rotating producer (g & 7) so no warp is the permanent straggler.
// Tried and rejected with evidence: early boundary-cross (3x: register
// live-range -> address rematerialization), in-kernel prep overlap (1x:
// chip-wide convoy serialization, tensor 45%). Do not revisit.
// ----------------------------------------------------------------------------
struct TileCoord { int m0, n0; };

__device__ __forceinline__ TileCoord tile_coord(int cta, int stride, int ti) {
    int t = cta + ti * stride;
    TileCoord tc;
    tc.n0 = (t & (TILES_N - 1)) * BN;
    tc.m0 = (t >> 4) * BM;
    return tc;
}

__device__ __forceinline__ void issue_chunk(
    int j, int cta, int stride, uint32_t sb,
    const CUtensorMap* pa, const CUtensorMap* pb, uint32_t full0)
{
    TileCoord tc = tile_coord(cta, stride, j >> 6);
    int k = (j & 63) * BK;
    int s = j & (STAGES - 1);
    uint32_t st = sb + 1024 + s * STAGE_BYTES;
    MBARRIER_EXPECT_TX(full0 + s * 8, (uint32_t)STAGE_BYTES);
    TMA_LOAD_2D(st,         pa, k, tc.m0, full0 + s * 8);
    TMA_LOAD_2D(st + 16384, pb, k, tc.n0, full0 + s * 8);
}

__global__ void __launch_bounds__(THREADS, 1) gemm_f16_kernel(
    const __grid_constant__ CUtensorMap tma_a,
    const __grid_constant__ CUtensorMap tma_b,
    const float* __restrict__ bias,
    float* __restrict__ out)
{
    extern __shared__ char smem_raw[];
    char* smem = (char*)(((uintptr_t)smem_raw + 1023) & ~(uintptr_t)1023);
    const uint32_t sb = smem_u32(smem);

    const int tid  = threadIdx.x;
    const int wid  = tid >> 5;
    const int lane = tid & 31;
    const int wm   = wid >> 2;   // 0..1 (M), warp tile M=64
    const int wn   = wid & 3;    // 0..3 (N), warp tile N=64

    const int cta    = blockIdx.x;
    const int stride = gridDim.x;
    const int cnt    = (TILES - cta + stride - 1) / stride;  // tiles owned
    const int total  = cnt * K_ITERS;                        // chunks owned (mult of 64)

    const uint32_t FULL0  = sb;        // 4 x 8B
    const uint32_t EMPTY0 = sb + 64;   // 4 x 8B

    if (tid == 0) {
        #pragma unroll
        for (int s = 0; s < STAGES; ++s) {
            MBARRIER_INIT(FULL0 + s * 8, 1);
            MBARRIER_INIT(EMPTY0 + s * 8, 8);   // 8 warps arrive
        }
        asm volatile("fence.proxy.async.shared::cta;" ::: "memory");
    }
    __syncthreads();

    // Prologue: issue chunks 0..STAGES-2
    if (tid == 0) {
        #pragma unroll
        for (int j = 0; j < STAGES - 1; ++j)
            if (j < total) issue_chunk(j, cta, stride, sb, &tma_a, &tma_b, FULL0);
    }

    // Per-thread ldmatrix address components (SW128 swizzle on 128B rows)
    const uint32_t a_row = (uint32_t)(wm * 64 + (lane & 15));
    const uint32_t a_k0  = (uint32_t)((lane >> 4) << 4);            // bytes
    const uint32_t b_row = (uint32_t)(wn * 64 + (lane & 7) + ((lane >> 4) << 3));
    const uint32_t b_k0  = (uint32_t)(((lane >> 3) & 1) << 4);      // bytes
    const uint32_t swz   = (uint32_t)((lane & 7) << 4);             // same for A & B

    // Hoisted per-thread base addresses and precomputed swizzled k-offsets.
    // Full expression ((ks*32 + k0) ^ swz) precomputed — XOR covers bits 4-6
    // which overlap ks*32 (bits 5-6), so it must NOT be split.
    const uint32_t aBase = sb + 1024 + a_row * 128;
    const uint32_t bBase = sb + 1024 + 16384 + b_row * 128;
    uint32_t aK[4], bK[4];
    #pragma unroll
    for (int ks = 0; ks < 4; ++ks) {
        aK[ks] = ((uint32_t)(ks * 32) + a_k0) ^ swz;
        bK[ks] = ((uint32_t)(ks * 32) + b_k0) ^ swz;
    }

    float c[4][8][4];
    #pragma unroll
    for (int t = 0; t < 4; ++t)
        #pragma unroll
        for (int n = 0; n < 8; ++n)
            #pragma unroll
            for (int k = 0; k < 4; ++k) c[t][n][k] = 0.0f;

    // Double-buffered fragments (ks-level pipelining)
    uint32_t af[2][4][4], bf[2][4][4];

    #pragma unroll 1
    for (int gb = 0; gb < total; gb += STAGES) {
        const int par = (gb >> 2) & 1;   // full-barrier parity, same for group

        #pragma unroll
        for (int s = 0; s < STAGES; ++s) {
            const int g = gb + s;

            // Rotating producer: warp (g & 7), lane 0, issues chunk g+STAGES-1.
            if (wid == (g & 7) && lane == 0) {
                int j = g + STAGES - 1;
                if (j < total) {
                    const int sj = (s + STAGES - 1) & (STAGES - 1);
                    if (j >= STAGES)
                        MBARRIER_WAIT_PARITY(EMPTY0 + sj * 8, ((j >> 2) + 1) & 1);
                    issue_chunk(j, cta, stride, sb, &tma_a, &tma_b, FULL0);
                }
            }

            MBARRIER_WAIT_PARITY(FULL0 + s * 8, par);

            const uint32_t aS = aBase + s * STAGE_BYTES;   // compile-time stage term
            const uint32_t bS = bBase + s * STAGE_BYTES;

            // Prefetch ks=0 fragments into buffer 0
            #pragma unroll
            for (int t = 0; t < 4; ++t)
                LDSM_X4(af[0][t][0], af[0][t][1], af[0][t][2], af[0][t][3],
                        aS + t * (16 * 128) + aK[0]);
            #pragma unroll
            for (int gg = 0; gg < 4; ++gg)
                LDSM_X4(bf[0][gg][0], bf[0][gg][1], bf[0][gg][2], bf[0][gg][3],
                        bS + gg * (16 * 128) + bK[0]);

            #pragma unroll
            for (int ks = 0; ks < 4; ++ks) {
                const int cur = ks & 1;
                if (ks < 3) {
                    // Prefetch (g, ks+1) fragments into the other buffer
                    const int nxt = cur ^ 1;
                    #pragma unroll
                    for (int t = 0; t < 4; ++t)
                        LDSM_X4(af[nxt][t][0], af[nxt][t][1], af[nxt][t][2], af[nxt][t][3],
                                aS + t * (16 * 128) + aK[ks + 1]);
                    #pragma unroll
                    for (int gg = 0; gg < 4; ++gg)
                        LDSM_X4(bf[nxt][gg][0], bf[nxt][gg][1], bf[nxt][gg][2], bf[nxt][gg][3],
                                bS + gg * (16 * 128) + bK[ks + 1]);
                } else {
                    // All smem reads for this stage issued; release it so TMA
                    // refills while the final MMA block runs on registers.
                    __syncwarp();
                    if (lane == 0) MBARRIER_ARRIVE(EMPTY0 + s * 8);
                }
                #pragma unroll
                for (int t = 0; t < 4; ++t) {
                    #pragma unroll
                    for (int gg = 0; gg < 4; ++gg) {
                        MMA16816(c[t][2 * gg],     af[cur][t], bf[cur][gg][0], bf[cur][gg][1]);
                        MMA16816(c[t][2 * gg + 1], af[cur][t], bf[cur][gg][2], bf[cur][gg][3]);
                    }
                }
            }

            // ---- Tile boundary: epilogue + accumulator reset. Reachable only
            // at s == 3 (64 chunks/tile, 4 | 64). TMA lookahead is already
            // filling the next tile's stages.
            if (s == STAGES - 1 && ((g & 63) == 63)) {
                TileCoord tc = tile_coord(cta, stride, g >> 6);
                const int m_base = tc.m0 + wm * 64 + (lane >> 2);
                const int n_base = tc.n0 + wn * 64 + (lane & 3) * 2;

                #pragma unroll
                for (int t = 0; t < 4; ++t) {
                    #pragma unroll
                    for (int nt = 0; nt < 8; ++nt) {
                        const int col = n_base + nt * 8;
                        const float2 bv = *reinterpret_cast<const float2*>(bias + col);
                        const int r0 = m_base + t * 16;
                        float2 v0, v1;
                        v0.x = c[t][nt][0] + bv.x;
                        v0.y = c[t][nt][1] + bv.y;
                        v1.x = c[t][nt][2] + bv.x;
                        v1.y = c[t][nt][3] + bv.y;
                        *reinterpret_cast<float2*>(out + (size_t)r0 * OUT_DIM + col) = v0;
                        *reinterpret_cast<float2*>(out + (size_t)(r0 + 8) * OUT_DIM + col) = v1;
                        c[t][nt][0] = 0.0f; c[t][nt][1] = 0.0f;
                        c[t][nt][2] = 0.0f; c[t][nt][3] = 0.0f;
                    }
                }
            }
        }
    }
}

// ----------------------------------------------------------------------------
// Host launcher
// ----------------------------------------------------------------------------
typedef CUresult (CUDAAPI *PFN_tmap_encode)(
    CUtensorMap*, CUtensorMapDataType, cuuint32_t, void*,
    const cuuint64_t*, const cuuint64_t*, const cuuint32_t*, const cuuint32_t*,
    CUtensorMapInterleave, CUtensorMapSwizzle, CUtensorMapL2promotion,
    CUtensorMapFloatOOBfill);

extern "C" void kernel_launch(void* const* d_in, const int* in_sizes, int n_in,
                              void* d_out, int out_size)
{
    const float*   x    = (const float*)d_in[0];
    const float*   wh   = (const float*)d_in[1];
    const float*   wmed = (const float*)d_in[2];   // fp16 promoted to fp32 by harness
    const int*     wl   = (const int*)d_in[3];
    const float*   ls   = (const float*)d_in[6];
    const float*   bias = (const float*)d_in[7];
    float* out = (float*)d_out;

    void* w16p = nullptr;
    void* x16p = nullptr;
    cudaGetSymbolAddress(&w16p, g_w16);
    cudaGetSymbolAddress(&x16p, g_x16);

    // Resolve cuTensorMapEncodeTiled through the runtime (no -lcuda needed).
    PFN_tmap_encode encode = nullptr;
    cudaDriverEntryPointQueryResult qres;
    cudaGetDriverEntryPointByVersion("cuTensorMapEncodeTiled", (void**)&encode,
                                     12000, cudaEnableDefault, &qres);

    CUtensorMap tma_a, tma_b;
    {
        cuuint64_t dims[2]    = { IN_DIM, M_TOTAL };
        cuuint64_t strides[1] = { IN_DIM * sizeof(__half) };
        cuuint32_t box[2]     = { BK, BM };           // 64 x 128
        cuuint32_t es[2]      = { 1, 1 };
        encode(&tma_a, CU_TENSOR_MAP_DATA_TYPE_FLOAT16, 2, x16p,
               dims, strides, box, es,
               CU_TENSOR_MAP_INTERLEAVE_NONE, CU_TENSOR_MAP_SWIZZLE_128B,
               CU_TENSOR_MAP_L2_PROMOTION_L2_128B, CU_TENSOR_MAP_FLOAT_OOB_FILL_NONE);
    }
    {
        cuuint64_t dims[2]    = { IN_DIM, OUT_DIM };
        cuuint64_t strides[1] = { IN_DIM * sizeof(__half) };
        cuuint32_t box[2]     = { BK, BN };           // 64 x 256
        cuuint32_t es[2]      = { 1, 1 };
        encode(&tma_b, CU_TENSOR_MAP_DATA_TYPE_FLOAT16, 2, w16p,
               dims, strides, box, es,
               CU_TENSOR_MAP_INTERLEAVE_NONE, CU_TENSOR_MAP_SWIZZLE_128B,
               CU_TENSOR_MAP_L2_PROMOTION_L2_128B, CU_TENSOR_MAP_FLOAT_OOB_FILL_NONE);
    }

    // Kernel 1: fused weight reconstruction + x conversion.
    // 2 independent coalesced streams per thread -> 8192 blocks per path.
    dim3 pgrid(PREP_BLKS, 2);
    prep_kernel<<<pgrid, 256>>>(
        (const float4*)wh, (const float4*)wmed, (const int4*)wl, ls,
        (uint2*)w16p, (const float4*)x, (uint4*)x16p);

    // Kernel 2: persistent GEMM — one CTA per SM.
    int dev = 0, sm_count = 148;
    cudaGetDevice(&dev);
    cudaDeviceGetAttribute(&sm_count, cudaDevAttrMultiProcessorCount, dev);
    if (sm_count > TILES) sm_count = TILES;
    cudaFuncSetAttribute(gemm_f16_kernel,
                         cudaFuncAttributeMaxDynamicSharedMemorySize, SMEM_ALLOC);
    gemm_f16_kernel<<<sm_count, THREADS, SMEM_ALLOC>>>(tma_a, tma_b, bias, out);
}